// round 4
// baseline (speedup 1.0000x reference)
#include <cuda_runtime.h>
#include <cuda_fp16.h>
#include <stdint.h>

// Problem constants (fixed by the reference)
#define kBatch 32
#define kQ     16
#define kHq    32
#define kHkv   8
#define kG     4
#define kD     128
#define kPage  16
#define kPPS   256
#define kK     4096
#define kTile  32

// fp16 smem tiles: row = 128 halves + 8 pad = 136 halves (272B)
#define kRowH   136
#define kTileH  (kTile*kRowH)        // 4352 halves per K or V tile
#define kStageH (2*kTileH)           // 8704 halves (K+V) per stage
#define kNStg   6
#define kSmemBytes (kNStg*kStageH*2 + 64*4)   // 104448 + 256 = 104704

// Split-KV schedule: 5 chunks; chunk s covers tiles [26s, 26s+nt), nt=26 (s<4) / 24 (s=4)
#define kSplit   5
#define kItems   (kBatch*kHkv*kSplit)   // 1280 CTAs, one item each (HW load balance)

// Scratch: unnormalized partial O + per-row (m, l) in log2 domain
__device__ float g_opart[(size_t)kSplit * 512 * 4096];        // 40 MB
__device__ float g_ml[kSplit * kBatch * kHq * kQ * 2];        // 320 KB

__device__ __forceinline__ uint32_t packh2(float lo, float hi){
    __half2 h = __floats2half2_rn(lo, hi);
    return *reinterpret_cast<uint32_t*>(&h);
}
__device__ __forceinline__ float ex2f(float x){
    float y; asm("ex2.approx.ftz.f32 %0, %1;" : "=f"(y) : "f"(x)); return y;
}
__device__ __forceinline__ void mma16816(float* c, const uint32_t* a, uint32_t b0, uint32_t b1){
    asm volatile(
      "mma.sync.aligned.m16n8k16.row.col.f32.f16.f16.f32 "
      "{%0,%1,%2,%3}, {%4,%5,%6,%7}, {%8,%9}, {%0,%1,%2,%3};\n"
      : "+f"(c[0]), "+f"(c[1]), "+f"(c[2]), "+f"(c[3])
      : "r"(a[0]), "r"(a[1]), "r"(a[2]), "r"(a[3]), "r"(b0), "r"(b1));
}
__device__ __forceinline__ void ldsm_x4(uint32_t& r0, uint32_t& r1, uint32_t& r2, uint32_t& r3, uint32_t a){
    asm volatile("ldmatrix.sync.aligned.m8n8.x4.shared.b16 {%0,%1,%2,%3}, [%4];"
                 : "=r"(r0),"=r"(r1),"=r"(r2),"=r"(r3) : "r"(a));
}
__device__ __forceinline__ void ldsm_x4t(uint32_t& r0, uint32_t& r1, uint32_t& r2, uint32_t& r3, uint32_t a){
    asm volatile("ldmatrix.sync.aligned.m8n8.x4.trans.shared.b16 {%0,%1,%2,%3}, [%4];"
                 : "=r"(r0),"=r"(r1),"=r"(r2),"=r"(r3) : "r"(a));
}
__device__ __forceinline__ void sts64(uint32_t addr, uint32_t a, uint32_t b){
    asm volatile("st.shared.v2.b32 [%0], {%1,%2};" :: "r"(addr), "r"(a), "r"(b));
}
__device__ __forceinline__ void bar_sync(int id, int cnt){
    asm volatile("bar.sync %0, %1;" :: "r"(id), "r"(cnt) : "memory");
}
__device__ __forceinline__ void bar_arrive(int id, int cnt){
    asm volatile("bar.arrive %0, %1;" :: "r"(id), "r"(cnt) : "memory");
}
// barrier ids: FULL(s) = 1+s (1..6), EMPTY(s) = 7+s (7..12), producer-internal = 14

__global__ __launch_bounds__(192, 2)
void paged_gqa_part(const float* __restrict__ q,
                    const float* __restrict__ kc,
                    const float* __restrict__ vc,
                    const int*   __restrict__ pt)
{
    extern __shared__ __align__(16) char smem[];
    int* pts = (int*)(smem + kNStg*kStageH*2);
    const uint32_t smem_s = (uint32_t)__cvta_generic_to_shared(smem);

    const int tid = threadIdx.x;
    const int item = blockIdx.x;
    const int s   = item >> 8;
    const int rem = item & 255;
    const int b   = rem >> 3;
    const int h   = rem & 7;
    const int tile0 = 26 * s;
    const int nt    = (s == 4) ? 24 : 26;

    if (tid >= 128){
        // ======================= PRODUCER (warps 4-5) =======================
        const int pl = tid - 128;           // 0..63
        if (pl < 2*nt) pts[pl] = pt[b*kPPS + 2*tile0 + pl];
        bar_sync(14, 64);

        const int co  = (pl & 31) * 4;      // float (=half) column offset, fixed per lane
        const int rhi = pl >> 5;            // 0/1 : even/odd rows

        #pragma unroll 1
        for (int t = 0; t < nt; t++){
            const int st = t % kNStg;
            bar_sync(7 + st, 192);          // wait EMPTY
            const uint32_t kdst0 = smem_s + (uint32_t)(st*kStageH + co)*2;
            #pragma unroll
            for (int i = 0; i < 16; i++){
                const int r = 2*i + rhi;
                const int p = t*kTile + r;
                const size_t gb = ((size_t)(pts[p >> 4]*kPage + (p & 15))*kHkv + h)*kD + co;
                float4 kv = *(const float4*)(kc + gb);
                float4 vv = *(const float4*)(vc + gb);
                const uint32_t ka = kdst0 + (uint32_t)(r*kRowH)*2;
                sts64(ka,            packh2(kv.x, kv.y), packh2(kv.z, kv.w));
                sts64(ka + kTileH*2, packh2(vv.x, vv.y), packh2(vv.z, vv.w));
            }
            asm volatile("membar.cta;" ::: "memory");
            bar_arrive(1 + st, 192);        // signal FULL
        }
        return;
    }

    // ========================= CONSUMER (warps 0-3) =========================
    const int w = tid >> 5, lane = tid & 31;

    // pre-arrive all EMPTY barriers so producers can start filling immediately
    #pragma unroll
    for (int st = 0; st < kNStg; st++) bar_arrive(7 + st, 192);

    // Q fragments, pre-scaled by log2e/sqrt(D); warp = GQA lane g
    const float scale = 1.4426950408889634f * rsqrtf((float)kD);
    uint32_t qf[8][4];
    {
        const int r0 = lane >> 2;
        const int c0 = (lane & 3) * 2;
        const float* q0 = q + (((size_t)(b*kQ + r0    ))*kHq + h*kG + w)*kD;
        const float* q1 = q + (((size_t)(b*kQ + r0 + 8))*kHq + h*kG + w)*kD;
        #pragma unroll
        for (int kk = 0; kk < 8; kk++){
            const int c = c0 + kk*16;
            float2 x0 = *(const float2*)(q0 + c);
            float2 x1 = *(const float2*)(q1 + c);
            float2 x2 = *(const float2*)(q0 + c + 8);
            float2 x3 = *(const float2*)(q1 + c + 8);
            qf[kk][0] = packh2(x0.x*scale, x0.y*scale);
            qf[kk][1] = packh2(x1.x*scale, x1.y*scale);
            qf[kk][2] = packh2(x2.x*scale, x2.y*scale);
            qf[kk][3] = packh2(x3.x*scale, x3.y*scale);
        }
    }

    // per-lane ldmatrix address bases (byte offsets within a tile)
    const int r8  = lane & 7;
    const int b8  = (lane >> 3) & 1;
    const int b16 = (lane >> 4) & 1;
    const uint32_t sc_off = (uint32_t)(((b16*8 + r8)*kRowH + b8*8)  * 2); // score: non-trans on K
    const uint32_t pv_off = (uint32_t)(((b8*8  + r8)*kRowH + b16*8) * 2); // PV: trans on V

    float o[16][4];
    #pragma unroll
    for (int j = 0; j < 16; j++){ o[j][0]=o[j][1]=o[j][2]=o[j][3]=0.f; }
    float m0 = -1e30f, m1 = -1e30f, l0 = 0.f, l1 = 0.f;

    #pragma unroll 1
    for (int t = 0; t < nt; t++){
        const int st = t % kNStg;
        bar_sync(1 + st, 192);              // wait FULL
        const uint32_t kst = smem_s + (uint32_t)(st*kStageH)*2;
        const uint32_t vst = kst + (uint32_t)kTileH*2;

        // ---- scores S[16 x 32] = Qw @ Ktile^T  (log2-scaled)
        float sc[4][4];
        #pragma unroll
        for (int j = 0; j < 4; j++) sc[j][0]=sc[j][1]=sc[j][2]=sc[j][3]=0.f;

        #pragma unroll
        for (int kk = 0; kk < 8; kk++){
            #pragma unroll
            for (int jp = 0; jp < 2; jp++){
                uint32_t r0,r1,r2,r3;
                ldsm_x4(r0,r1,r2,r3, kst + sc_off + (uint32_t)(jp*4352 + kk*32));
                mma16816(sc[2*jp  ], qf[kk], r0, r1);
                mma16816(sc[2*jp+1], qf[kk], r2, r3);
            }
        }

        // causal mask: only the globally-last tile (tile 127) is partial
        if (tile0 + t == 127){
            const int r0q = lane >> 2;
            #pragma unroll
            for (int j = 0; j < 4; j++){
                const int col = 8*j + (lane&3)*2;
                if (col     > 16 + r0q) sc[j][0] = -1e30f;
                if (col + 1 > 16 + r0q) sc[j][1] = -1e30f;
                if (col     > 24 + r0q) sc[j][2] = -1e30f;
                if (col + 1 > 24 + r0q) sc[j][3] = -1e30f;
            }
        }

        // ---- online softmax (base 2)
        float mx0 = fmaxf(fmaxf(sc[0][0],sc[0][1]), fmaxf(sc[1][0],sc[1][1]));
        mx0 = fmaxf(mx0, fmaxf(fmaxf(sc[2][0],sc[2][1]), fmaxf(sc[3][0],sc[3][1])));
        float mx1 = fmaxf(fmaxf(sc[0][2],sc[0][3]), fmaxf(sc[1][2],sc[1][3]));
        mx1 = fmaxf(mx1, fmaxf(fmaxf(sc[2][2],sc[2][3]), fmaxf(sc[3][2],sc[3][3])));
        mx0 = fmaxf(mx0, __shfl_xor_sync(0xffffffffu, mx0, 1));
        mx0 = fmaxf(mx0, __shfl_xor_sync(0xffffffffu, mx0, 2));
        mx1 = fmaxf(mx1, __shfl_xor_sync(0xffffffffu, mx1, 1));
        mx1 = fmaxf(mx1, __shfl_xor_sync(0xffffffffu, mx1, 2));
        const float nm0 = fmaxf(m0, mx0), nm1 = fmaxf(m1, mx1);
        const float a0 = ex2f(m0 - nm0), a1 = ex2f(m1 - nm1);
        m0 = nm0; m1 = nm1;
        l0 *= a0; l1 *= a1;
        #pragma unroll
        for (int j = 0; j < 4; j++){
            sc[j][0] = ex2f(sc[j][0] - m0);
            sc[j][1] = ex2f(sc[j][1] - m0);
            sc[j][2] = ex2f(sc[j][2] - m1);
            sc[j][3] = ex2f(sc[j][3] - m1);
            l0 += sc[j][0] + sc[j][1];
            l1 += sc[j][2] + sc[j][3];
        }
        if (__ballot_sync(0xffffffffu, (a0 != 1.f) || (a1 != 1.f))){
            #pragma unroll
            for (int j = 0; j < 16; j++){
                o[j][0]*=a0; o[j][1]*=a0; o[j][2]*=a1; o[j][3]*=a1;
            }
        }

        // ---- O += P @ Vtile  (P C-frags map exactly onto A-frags; V B-frags via ldmatrix.trans)
        #pragma unroll
        for (int k2 = 0; k2 < 2; k2++){
            uint32_t pa[4];
            pa[0] = packh2(sc[2*k2  ][0], sc[2*k2  ][1]);
            pa[1] = packh2(sc[2*k2  ][2], sc[2*k2  ][3]);
            pa[2] = packh2(sc[2*k2+1][0], sc[2*k2+1][1]);
            pa[3] = packh2(sc[2*k2+1][2], sc[2*k2+1][3]);
            #pragma unroll
            for (int jdp = 0; jdp < 8; jdp++){
                uint32_t r0,r1,r2,r3;
                ldsm_x4t(r0,r1,r2,r3, vst + pv_off + (uint32_t)(k2*4352 + jdp*32));
                mma16816(o[2*jdp  ], pa, r0, r1);
                mma16816(o[2*jdp+1], pa, r2, r3);
            }
        }
        bar_arrive(7 + st, 192);            // signal EMPTY
    }

    // ---- epilogue: quad-reduce l, store UNNORMALIZED partial O + (m,l)
    l0 += __shfl_xor_sync(0xffffffffu, l0, 1);
    l0 += __shfl_xor_sync(0xffffffffu, l0, 2);
    l1 += __shfl_xor_sync(0xffffffffu, l1, 1);
    l1 += __shfl_xor_sync(0xffffffffu, l1, 2);

    const int r0 = lane >> 2;
    const int hq = h*kG + w;
    float* o0 = g_opart + (((size_t)(s*512 + b*kQ + r0    ))*4096) + hq*kD + (lane&3)*2;
    float* o1 = g_opart + (((size_t)(s*512 + b*kQ + r0 + 8))*4096) + hq*kD + (lane&3)*2;
    #pragma unroll
    for (int jd = 0; jd < 16; jd++){
        *(float2*)(o0 + jd*8) = make_float2(o[jd][0], o[jd][1]);
        *(float2*)(o1 + jd*8) = make_float2(o[jd][2], o[jd][3]);
    }
    if ((lane & 3) == 0){
        const int i0 = ((((s*kBatch + b)*kHq + hq)*kQ) + r0)*2;
        g_ml[i0]      = m0; g_ml[i0 + 1]  = l0;
        g_ml[i0 + 16] = m1; g_ml[i0 + 17] = l1;   // rows r0+8
    }
}

// merge kSplit partial results: out = sum_s 2^(m_s-m*) O_s / sum_s 2^(m_s-m*) l_s
__global__ __launch_bounds__(256)
void paged_gqa_combine(float* __restrict__ out)
{
    const int idx = blockIdx.x * 256 + threadIdx.x;     // [0, 512*1024)
    const int row = idx >> 10;            // b*16 + q
    const int c4  = idx & 1023;           // float4 column
    const int b   = row >> 4;
    const int qi  = row & 15;
    const int hq  = c4 >> 5;              // (c4*4) / 128

    float m[kSplit], l[kSplit];
    float mstar = -1e30f;
    #pragma unroll
    for (int s = 0; s < kSplit; s++){
        const int i0 = ((((s*kBatch + b)*kHq + hq)*kQ) + qi)*2;
        m[s] = g_ml[i0]; l[s] = g_ml[i0 + 1];
        mstar = fmaxf(mstar, m[s]);
    }
    float denom = 0.f;
    float4 acc = make_float4(0.f, 0.f, 0.f, 0.f);
    #pragma unroll
    for (int s = 0; s < kSplit; s++){
        const float wgt = ex2f(m[s] - mstar);
        denom += wgt * l[s];
        const float4 v = *(const float4*)(g_opart + ((size_t)(s*512 + row))*4096 + c4*4);
        acc.x += wgt*v.x; acc.y += wgt*v.y; acc.z += wgt*v.z; acc.w += wgt*v.w;
    }
    const float inv = 1.0f / denom;
    acc.x *= inv; acc.y *= inv; acc.z *= inv; acc.w *= inv;
    ((float4*)out)[idx] = acc;
}

extern "C" void kernel_launch(void* const* d_in, const int* in_sizes, int n_in,
                              void* d_out, int out_size)
{
    const float* q  = (const float*)d_in[0];   // [32,16,32,128] f32
    const float* kc = (const float*)d_in[1];   // [8192,16,8,128] f32
    const float* vc = (const float*)d_in[2];   // [8192,16,8,128] f32
    const int*   pt = (const int*)  d_in[3];   // [32,256] i32
    float* out = (float*)d_out;                // [512,4096] f32

    cudaFuncSetAttribute(paged_gqa_part,
                         cudaFuncAttributeMaxDynamicSharedMemorySize, kSmemBytes);
    paged_gqa_part<<<kItems, 192, kSmemBytes>>>(q, kc, vc, pt);
    paged_gqa_combine<<<(512*1024)/256, 256>>>(out);
}

// round 6
// speedup vs baseline: 3.9053x; 3.9053x over previous
#include <cuda_runtime.h>
#include <cuda_fp16.h>
#include <stdint.h>

// Problem constants (fixed by the reference)
#define kBatch 32
#define kQ     16
#define kHq    32
#define kHkv   8
#define kG     4
#define kD     128
#define kPage  16
#define kPPS   256
#define kK     4096
#define kTile  32

// fp16 smem tiles: row = 128 halves + 8 pad = 136 halves (272B)
#define kRowH   136
#define kTileH  (kTile*kRowH)        // 4352 halves per K or V tile
#define kStageH (2*kTileH)           // 8704 halves (K+V) per stage
#define kNStg   6
#define kSmemBytes (kNStg*kStageH*2 + 64*4)   // 104448 + 256 = 104704

// Split-KV schedule: 5 chunks; chunk s covers tiles [26s, 26s+nt), nt=26 (s<4) / 24 (s=4)
#define kSplit   5
#define kItems   (kBatch*kHkv*kSplit)   // 1280 CTAs, one item each (HW load balance)

// Scratch: unnormalized partial O + per-row (m, l) in log2 domain
__device__ float g_opart[(size_t)kSplit * 512 * 4096];        // 40 MB
__device__ float g_ml[kSplit * kBatch * kHq * kQ * 2];        // 320 KB

__device__ __forceinline__ uint32_t packh2(float lo, float hi){
    __half2 h = __floats2half2_rn(lo, hi);
    return *reinterpret_cast<uint32_t*>(&h);
}
__device__ __forceinline__ float ex2f(float x){
    float y; asm("ex2.approx.ftz.f32 %0, %1;" : "=f"(y) : "f"(x)); return y;
}
__device__ __forceinline__ void mma16816(float* c, const uint32_t* a, uint32_t b0, uint32_t b1){
    asm volatile(
      "mma.sync.aligned.m16n8k16.row.col.f32.f16.f16.f32 "
      "{%0,%1,%2,%3}, {%4,%5,%6,%7}, {%8,%9}, {%0,%1,%2,%3};\n"
      : "+f"(c[0]), "+f"(c[1]), "+f"(c[2]), "+f"(c[3])
      : "r"(a[0]), "r"(a[1]), "r"(a[2]), "r"(a[3]), "r"(b0), "r"(b1));
}
__device__ __forceinline__ void ldsm_x4(uint32_t& r0, uint32_t& r1, uint32_t& r2, uint32_t& r3, uint32_t a){
    asm volatile("ldmatrix.sync.aligned.m8n8.x4.shared.b16 {%0,%1,%2,%3}, [%4];"
                 : "=r"(r0),"=r"(r1),"=r"(r2),"=r"(r3) : "r"(a));
}
__device__ __forceinline__ void ldsm_x4t(uint32_t& r0, uint32_t& r1, uint32_t& r2, uint32_t& r3, uint32_t a){
    asm volatile("ldmatrix.sync.aligned.m8n8.x4.trans.shared.b16 {%0,%1,%2,%3}, [%4];"
                 : "=r"(r0),"=r"(r1),"=r"(r2),"=r"(r3) : "r"(a));
}
__device__ __forceinline__ void sts64(uint32_t addr, uint32_t a, uint32_t b){
    asm volatile("st.shared.v2.b32 [%0], {%1,%2};" :: "r"(addr), "r"(a), "r"(b));
}
__device__ __forceinline__ void bar_sync(int id, int cnt){
    asm volatile("bar.sync %0, %1;" :: "r"(id), "r"(cnt) : "memory");
}
__device__ __forceinline__ void bar_arrive(int id, int cnt){
    asm volatile("bar.arrive %0, %1;" :: "r"(id), "r"(cnt) : "memory");
}
// barrier ids: FULL(s) = 1+s (1..6), EMPTY(s) = 7+s (7..12), producer-internal = 14

__global__ __launch_bounds__(192, 2)
void paged_gqa_part(const float* __restrict__ q,
                    const float* __restrict__ kc,
                    const float* __restrict__ vc,
                    const int*   __restrict__ pt)
{
    extern __shared__ __align__(16) char smem[];
    int* pts = (int*)(smem + kNStg*kStageH*2);
    const uint32_t smem_s = (uint32_t)__cvta_generic_to_shared(smem);

    const int tid = threadIdx.x;
    const int item = blockIdx.x;
    const int s   = item >> 8;
    const int rem = item & 255;
    const int b   = rem >> 3;
    const int h   = rem & 7;
    const int tile0 = 26 * s;
    const int nt    = (s == 4) ? 24 : 26;

    if (tid >= 128){
        // ======================= PRODUCER (warps 4-5) =======================
        const int pl = tid - 128;           // 0..63
        if (pl < 2*nt) pts[pl] = pt[b*kPPS + 2*tile0 + pl];
        bar_sync(14, 64);

        const int co  = (pl & 31) * 4;      // float (=half) column offset, fixed per lane
        const int rhi = pl >> 5;            // 0/1 : even/odd rows

        #pragma unroll 1
        for (int t = 0; t < nt; t++){
            const int st = t % kNStg;
            bar_sync(7 + st, 192);          // wait EMPTY
            const uint32_t kdst0 = smem_s + (uint32_t)(st*kStageH + co)*2;
            // phase-split: batch 16 independent LDG.128 (MLP=16), THEN convert+STS.
            // (volatile STS inside the load loop would fence LDG reordering -> MLP~2)
            #pragma unroll
            for (int half = 0; half < 2; half++){
                float4 kb[8], vb[8];
                #pragma unroll
                for (int i = 0; i < 8; i++){
                    const int r = 2*(half*8 + i) + rhi;
                    const int p = t*kTile + r;
                    const size_t gb = ((size_t)(pts[p >> 4]*kPage + (p & 15))*kHkv + h)*kD + co;
                    kb[i] = *(const float4*)(kc + gb);
                    vb[i] = *(const float4*)(vc + gb);
                }
                #pragma unroll
                for (int i = 0; i < 8; i++){
                    const int r = 2*(half*8 + i) + rhi;
                    const uint32_t ka = kdst0 + (uint32_t)(r*kRowH)*2;
                    sts64(ka,            packh2(kb[i].x, kb[i].y), packh2(kb[i].z, kb[i].w));
                    sts64(ka + kTileH*2, packh2(vb[i].x, vb[i].y), packh2(vb[i].z, vb[i].w));
                }
            }
            asm volatile("membar.cta;" ::: "memory");
            bar_arrive(1 + st, 192);        // signal FULL
        }
        return;
    }

    // ========================= CONSUMER (warps 0-3) =========================
    const int w = tid >> 5, lane = tid & 31;

    // pre-arrive all EMPTY barriers so producers can start filling immediately
    #pragma unroll
    for (int st = 0; st < kNStg; st++) bar_arrive(7 + st, 192);

    // Q fragments, pre-scaled by log2e/sqrt(D); warp = GQA lane g
    const float scale = 1.4426950408889634f * rsqrtf((float)kD);
    uint32_t qf[8][4];
    {
        const int r0 = lane >> 2;
        const int c0 = (lane & 3) * 2;
        const float* q0 = q + (((size_t)(b*kQ + r0    ))*kHq + h*kG + w)*kD;
        const float* q1 = q + (((size_t)(b*kQ + r0 + 8))*kHq + h*kG + w)*kD;
        #pragma unroll
        for (int kk = 0; kk < 8; kk++){
            const int c = c0 + kk*16;
            float2 x0 = *(const float2*)(q0 + c);
            float2 x1 = *(const float2*)(q1 + c);
            float2 x2 = *(const float2*)(q0 + c + 8);
            float2 x3 = *(const float2*)(q1 + c + 8);
            qf[kk][0] = packh2(x0.x*scale, x0.y*scale);
            qf[kk][1] = packh2(x1.x*scale, x1.y*scale);
            qf[kk][2] = packh2(x2.x*scale, x2.y*scale);
            qf[kk][3] = packh2(x3.x*scale, x3.y*scale);
        }
    }

    // per-lane ldmatrix address bases (byte offsets within a tile)
    const int r8  = lane & 7;
    const int b8  = (lane >> 3) & 1;
    const int b16 = (lane >> 4) & 1;
    const uint32_t sc_off = (uint32_t)(((b16*8 + r8)*kRowH + b8*8)  * 2); // score: non-trans on K
    const uint32_t pv_off = (uint32_t)(((b8*8  + r8)*kRowH + b16*8) * 2); // PV: trans on V

    float o[16][4];
    #pragma unroll
    for (int j = 0; j < 16; j++){ o[j][0]=o[j][1]=o[j][2]=o[j][3]=0.f; }
    float m0 = -1e30f, m1 = -1e30f, l0 = 0.f, l1 = 0.f;

    #pragma unroll 1
    for (int t = 0; t < nt; t++){
        const int st = t % kNStg;
        bar_sync(1 + st, 192);              // wait FULL
        const uint32_t kst = smem_s + (uint32_t)(st*kStageH)*2;
        const uint32_t vst = kst + (uint32_t)kTileH*2;

        // ---- scores S[16 x 32] = Qw @ Ktile^T  (log2-scaled)
        float sc[4][4];
        #pragma unroll
        for (int j = 0; j < 4; j++) sc[j][0]=sc[j][1]=sc[j][2]=sc[j][3]=0.f;

        #pragma unroll
        for (int kk = 0; kk < 8; kk++){
            #pragma unroll
            for (int jp = 0; jp < 2; jp++){
                uint32_t r0,r1,r2,r3;
                ldsm_x4(r0,r1,r2,r3, kst + sc_off + (uint32_t)(jp*4352 + kk*32));
                mma16816(sc[2*jp  ], qf[kk], r0, r1);
                mma16816(sc[2*jp+1], qf[kk], r2, r3);
            }
        }

        // causal mask: only the globally-last tile (tile 127) is partial
        if (tile0 + t == 127){
            const int r0q = lane >> 2;
            #pragma unroll
            for (int j = 0; j < 4; j++){
                const int col = 8*j + (lane&3)*2;
                if (col     > 16 + r0q) sc[j][0] = -1e30f;
                if (col + 1 > 16 + r0q) sc[j][1] = -1e30f;
                if (col     > 24 + r0q) sc[j][2] = -1e30f;
                if (col + 1 > 24 + r0q) sc[j][3] = -1e30f;
            }
        }

        // ---- online softmax (base 2)
        float mx0 = fmaxf(fmaxf(sc[0][0],sc[0][1]), fmaxf(sc[1][0],sc[1][1]));
        mx0 = fmaxf(mx0, fmaxf(fmaxf(sc[2][0],sc[2][1]), fmaxf(sc[3][0],sc[3][1])));
        float mx1 = fmaxf(fmaxf(sc[0][2],sc[0][3]), fmaxf(sc[1][2],sc[1][3]));
        mx1 = fmaxf(mx1, fmaxf(fmaxf(sc[2][2],sc[2][3]), fmaxf(sc[3][2],sc[3][3])));
        mx0 = fmaxf(mx0, __shfl_xor_sync(0xffffffffu, mx0, 1));
        mx0 = fmaxf(mx0, __shfl_xor_sync(0xffffffffu, mx0, 2));
        mx1 = fmaxf(mx1, __shfl_xor_sync(0xffffffffu, mx1, 1));
        mx1 = fmaxf(mx1, __shfl_xor_sync(0xffffffffu, mx1, 2));
        const float nm0 = fmaxf(m0, mx0), nm1 = fmaxf(m1, mx1);
        const float a0 = ex2f(m0 - nm0), a1 = ex2f(m1 - nm1);
        m0 = nm0; m1 = nm1;
        l0 *= a0; l1 *= a1;
        #pragma unroll
        for (int j = 0; j < 4; j++){
            sc[j][0] = ex2f(sc[j][0] - m0);
            sc[j][1] = ex2f(sc[j][1] - m0);
            sc[j][2] = ex2f(sc[j][2] - m1);
            sc[j][3] = ex2f(sc[j][3] - m1);
            l0 += sc[j][0] + sc[j][1];
            l1 += sc[j][2] + sc[j][3];
        }
        if (__ballot_sync(0xffffffffu, (a0 != 1.f) || (a1 != 1.f))){
            #pragma unroll
            for (int j = 0; j < 16; j++){
                o[j][0]*=a0; o[j][1]*=a0; o[j][2]*=a1; o[j][3]*=a1;
            }
        }

        // ---- O += P @ Vtile  (P C-frags map exactly onto A-frags; V B-frags via ldmatrix.trans)
        #pragma unroll
        for (int k2 = 0; k2 < 2; k2++){
            uint32_t pa[4];
            pa[0] = packh2(sc[2*k2  ][0], sc[2*k2  ][1]);
            pa[1] = packh2(sc[2*k2  ][2], sc[2*k2  ][3]);
            pa[2] = packh2(sc[2*k2+1][0], sc[2*k2+1][1]);
            pa[3] = packh2(sc[2*k2+1][2], sc[2*k2+1][3]);
            #pragma unroll
            for (int jdp = 0; jdp < 8; jdp++){
                uint32_t r0,r1,r2,r3;
                ldsm_x4t(r0,r1,r2,r3, vst + pv_off + (uint32_t)(k2*4352 + jdp*32));
                mma16816(o[2*jdp  ], pa, r0, r1);
                mma16816(o[2*jdp+1], pa, r2, r3);
            }
        }
        bar_arrive(7 + st, 192);            // signal EMPTY
    }

    // ---- epilogue: quad-reduce l, store UNNORMALIZED partial O + (m,l)
    l0 += __shfl_xor_sync(0xffffffffu, l0, 1);
    l0 += __shfl_xor_sync(0xffffffffu, l0, 2);
    l1 += __shfl_xor_sync(0xffffffffu, l1, 1);
    l1 += __shfl_xor_sync(0xffffffffu, l1, 2);

    const int r0 = lane >> 2;
    const int hq = h*kG + w;
    float* o0 = g_opart + (((size_t)(s*512 + b*kQ + r0    ))*4096) + hq*kD + (lane&3)*2;
    float* o1 = g_opart + (((size_t)(s*512 + b*kQ + r0 + 8))*4096) + hq*kD + (lane&3)*2;
    #pragma unroll
    for (int jd = 0; jd < 16; jd++){
        *(float2*)(o0 + jd*8) = make_float2(o[jd][0], o[jd][1]);
        *(float2*)(o1 + jd*8) = make_float2(o[jd][2], o[jd][3]);
    }
    if ((lane & 3) == 0){
        const int i0 = ((((s*kBatch + b)*kHq + hq)*kQ) + r0)*2;
        g_ml[i0]      = m0; g_ml[i0 + 1]  = l0;
        g_ml[i0 + 16] = m1; g_ml[i0 + 17] = l1;   // rows r0+8
    }
}

// merge kSplit partial results: out = sum_s 2^(m_s-m*) O_s / sum_s 2^(m_s-m*) l_s
__global__ __launch_bounds__(256)
void paged_gqa_combine(float* __restrict__ out)
{
    const int idx = blockIdx.x * 256 + threadIdx.x;     // [0, 512*1024)
    const int row = idx >> 10;            // b*16 + q
    const int c4  = idx & 1023;           // float4 column
    const int b   = row >> 4;
    const int qi  = row & 15;
    const int hq  = c4 >> 5;              // (c4*4) / 128

    float m[kSplit], l[kSplit];
    float mstar = -1e30f;
    #pragma unroll
    for (int s = 0; s < kSplit; s++){
        const int i0 = ((((s*kBatch + b)*kHq + hq)*kQ) + qi)*2;
        m[s] = g_ml[i0]; l[s] = g_ml[i0 + 1];
        mstar = fmaxf(mstar, m[s]);
    }
    float denom = 0.f;
    float4 acc = make_float4(0.f, 0.f, 0.f, 0.f);
    #pragma unroll
    for (int s = 0; s < kSplit; s++){
        const float wgt = ex2f(m[s] - mstar);
        denom += wgt * l[s];
        const float4 v = *(const float4*)(g_opart + ((size_t)(s*512 + row))*4096 + c4*4);
        acc.x += wgt*v.x; acc.y += wgt*v.y; acc.z += wgt*v.z; acc.w += wgt*v.w;
    }
    const float inv = 1.0f / denom;
    acc.x *= inv; acc.y *= inv; acc.z *= inv; acc.w *= inv;
    ((float4*)out)[idx] = acc;
}

extern "C" void kernel_launch(void* const* d_in, const int* in_sizes, int n_in,
                              void* d_out, int out_size)
{
    const float* q  = (const float*)d_in[0];   // [32,16,32,128] f32
    const float* kc = (const float*)d_in[1];   // [8192,16,8,128] f32
    const float* vc = (const float*)d_in[2];   // [8192,16,8,128] f32
    const int*   pt = (const int*)  d_in[3];   // [32,256] i32
    float* out = (float*)d_out;                // [512,4096] f32

    cudaFuncSetAttribute(paged_gqa_part,
                         cudaFuncAttributeMaxDynamicSharedMemorySize, kSmemBytes);
    paged_gqa_part<<<kItems, 192, kSmemBytes>>>(q, kc, vc, pt);
    paged_gqa_combine<<<(512*1024)/256, 256>>>(out);
}

// round 7
// speedup vs baseline: 3.9393x; 1.0087x over previous
#include <cuda_runtime.h>
#include <cuda_fp16.h>
#include <stdint.h>

// Problem constants (fixed by the reference)
#define kBatch 32
#define kQ     16
#define kHq    32
#define kHkv   8
#define kG     4
#define kD     128
#define kPage  16
#define kPPS   256
#define kK     4096
#define kTile  32

// fp16 smem tiles: row = 128 halves + 8 pad = 136 halves (272B)
#define kRowH   136
#define kTileH  (kTile*kRowH)        // 4352 halves per K or V tile
#define kStageH (2*kTileH)           // 8704 halves (K+V) per stage
#define kNStg   6
#define kSmemBytes (kNStg*kStageH*2 + 64*4)   // 104448 + 256 = 104704

// Split-KV schedule: 5 chunks; chunk s covers tiles [26s, 26s+nt), nt=26 (s<4) / 24 (s=4)
#define kSplit   5
#define kItems   (kBatch*kHkv*kSplit)   // 1280 CTAs, one item each (HW load balance)

// Scratch: unnormalized partial O + per-row (m, l) in log2 domain
__device__ float g_opart[(size_t)kSplit * 512 * 4096];        // 40 MB
__device__ float g_ml[kSplit * kBatch * kHq * kQ * 2];        // 320 KB

__device__ __forceinline__ uint32_t packh2(float lo, float hi){
    __half2 h = __floats2half2_rn(lo, hi);
    return *reinterpret_cast<uint32_t*>(&h);
}
__device__ __forceinline__ float ex2f(float x){
    float y; asm("ex2.approx.ftz.f32 %0, %1;" : "=f"(y) : "f"(x)); return y;
}
__device__ __forceinline__ void mma16816(float* c, const uint32_t* a, uint32_t b0, uint32_t b1){
    asm volatile(
      "mma.sync.aligned.m16n8k16.row.col.f32.f16.f16.f32 "
      "{%0,%1,%2,%3}, {%4,%5,%6,%7}, {%8,%9}, {%0,%1,%2,%3};\n"
      : "+f"(c[0]), "+f"(c[1]), "+f"(c[2]), "+f"(c[3])
      : "r"(a[0]), "r"(a[1]), "r"(a[2]), "r"(a[3]), "r"(b0), "r"(b1));
}
__device__ __forceinline__ void ldsm_x4(uint32_t& r0, uint32_t& r1, uint32_t& r2, uint32_t& r3, uint32_t a){
    asm volatile("ldmatrix.sync.aligned.m8n8.x4.shared.b16 {%0,%1,%2,%3}, [%4];"
                 : "=r"(r0),"=r"(r1),"=r"(r2),"=r"(r3) : "r"(a));
}
__device__ __forceinline__ void ldsm_x4t(uint32_t& r0, uint32_t& r1, uint32_t& r2, uint32_t& r3, uint32_t a){
    asm volatile("ldmatrix.sync.aligned.m8n8.x4.trans.shared.b16 {%0,%1,%2,%3}, [%4];"
                 : "=r"(r0),"=r"(r1),"=r"(r2),"=r"(r3) : "r"(a));
}
__device__ __forceinline__ void sts64(uint32_t addr, uint32_t a, uint32_t b){
    asm volatile("st.shared.v2.b32 [%0], {%1,%2};" :: "r"(addr), "r"(a), "r"(b));
}
__device__ __forceinline__ void bar_sync(int id, int cnt){
    asm volatile("bar.sync %0, %1;" :: "r"(id), "r"(cnt) : "memory");
}
__device__ __forceinline__ void bar_arrive(int id, int cnt){
    asm volatile("bar.arrive %0, %1;" :: "r"(id), "r"(cnt) : "memory");
}
// barrier ids: FULL(s) = 1+s (1..6), EMPTY(s) = 7+s (7..12), producer-internal = 14

__global__ __launch_bounds__(192, 2)
void paged_gqa_part(const float* __restrict__ q,
                    const float* __restrict__ kc,
                    const float* __restrict__ vc,
                    const int*   __restrict__ pt)
{
    extern __shared__ __align__(16) char smem[];
    int* pts = (int*)(smem + kNStg*kStageH*2);
    const uint32_t smem_s = (uint32_t)__cvta_generic_to_shared(smem);

    const int tid = threadIdx.x;
    const int item = blockIdx.x;
    const int s   = item >> 8;
    const int rem = item & 255;
    const int b   = rem >> 3;
    const int h   = rem & 7;
    const int tile0 = 26 * s;
    const int nt    = (s == 4) ? 24 : 26;

    if (tid >= 128){
        // ======================= PRODUCER (warps 4-5) =======================
        // Software-pipelined: tile t+1 is loaded into registers IMMEDIATELY after
        // tile t's FULL arrive, so the ~600cyc DRAM latency overlaps a full tile
        // of consumer compute instead of sitting on the stage handoff (R6 bug).
        const int pl = tid - 128;           // 0..63
        if (pl < 2*nt) pts[pl] = pt[b*kPPS + 2*tile0 + pl];
        bar_sync(14, 64);

        const int co  = (pl & 31) * 4;      // float (=half) column offset, fixed per lane
        const int rhi = pl >> 5;            // 0/1 : even/odd rows

        float4 kb[16], vb[16];
        // prologue: batch-load tile 0 (32 independent LDG.128, MLP=32)
        #pragma unroll
        for (int i = 0; i < 16; i++){
            const int r = 2*i + rhi;
            const size_t gb = ((size_t)(pts[r >> 4]*kPage + (r & 15))*kHkv + h)*kD + co;
            kb[i] = *(const float4*)(kc + gb);
            vb[i] = *(const float4*)(vc + gb);
        }

        #pragma unroll 1
        for (int t = 0; t < nt; t++){
            const int st = t % kNStg;
            bar_sync(7 + st, 192);          // wait EMPTY
            const uint32_t kdst0 = smem_s + (uint32_t)(st*kStageH + co)*2;
            #pragma unroll
            for (int i = 0; i < 16; i++){
                const int r = 2*i + rhi;
                const uint32_t ka = kdst0 + (uint32_t)(r*kRowH)*2;
                sts64(ka,            packh2(kb[i].x, kb[i].y), packh2(kb[i].z, kb[i].w));
                sts64(ka + kTileH*2, packh2(vb[i].x, vb[i].y), packh2(vb[i].z, vb[i].w));
            }
            asm volatile("membar.cta;" ::: "memory");
            bar_arrive(1 + st, 192);        // signal FULL
            if (t + 1 < nt){
                // issue next tile's loads now; latency hides behind consumer compute
                #pragma unroll
                for (int i = 0; i < 16; i++){
                    const int r = 2*i + rhi;
                    const int p = (t+1)*kTile + r;
                    const size_t gb = ((size_t)(pts[p >> 4]*kPage + (p & 15))*kHkv + h)*kD + co;
                    kb[i] = *(const float4*)(kc + gb);
                    vb[i] = *(const float4*)(vc + gb);
                }
            }
        }
        return;
    }

    // ========================= CONSUMER (warps 0-3) =========================
    const int w = tid >> 5, lane = tid & 31;

    // pre-arrive all EMPTY barriers so producers can start filling immediately
    #pragma unroll
    for (int st = 0; st < kNStg; st++) bar_arrive(7 + st, 192);

    // Q fragments, pre-scaled by log2e/sqrt(D); warp = GQA lane g
    const float scale = 1.4426950408889634f * rsqrtf((float)kD);
    uint32_t qf[8][4];
    {
        const int r0 = lane >> 2;
        const int c0 = (lane & 3) * 2;
        const float* q0 = q + (((size_t)(b*kQ + r0    ))*kHq + h*kG + w)*kD;
        const float* q1 = q + (((size_t)(b*kQ + r0 + 8))*kHq + h*kG + w)*kD;
        #pragma unroll
        for (int kk = 0; kk < 8; kk++){
            const int c = c0 + kk*16;
            float2 x0 = *(const float2*)(q0 + c);
            float2 x1 = *(const float2*)(q1 + c);
            float2 x2 = *(const float2*)(q0 + c + 8);
            float2 x3 = *(const float2*)(q1 + c + 8);
            qf[kk][0] = packh2(x0.x*scale, x0.y*scale);
            qf[kk][1] = packh2(x1.x*scale, x1.y*scale);
            qf[kk][2] = packh2(x2.x*scale, x2.y*scale);
            qf[kk][3] = packh2(x3.x*scale, x3.y*scale);
        }
    }

    // per-lane ldmatrix address bases (byte offsets within a tile)
    const int r8  = lane & 7;
    const int b8  = (lane >> 3) & 1;
    const int b16 = (lane >> 4) & 1;
    const uint32_t sc_off = (uint32_t)(((b16*8 + r8)*kRowH + b8*8)  * 2); // score: non-trans on K
    const uint32_t pv_off = (uint32_t)(((b8*8  + r8)*kRowH + b16*8) * 2); // PV: trans on V

    float o[16][4];
    #pragma unroll
    for (int j = 0; j < 16; j++){ o[j][0]=o[j][1]=o[j][2]=o[j][3]=0.f; }
    float m0 = -1e30f, m1 = -1e30f, l0 = 0.f, l1 = 0.f;

    #pragma unroll 1
    for (int t = 0; t < nt; t++){
        const int st = t % kNStg;
        bar_sync(1 + st, 192);              // wait FULL
        const uint32_t kst = smem_s + (uint32_t)(st*kStageH)*2;
        const uint32_t vst = kst + (uint32_t)kTileH*2;

        // ---- scores S[16 x 32] = Qw @ Ktile^T  (log2-scaled)
        float sc[4][4];
        #pragma unroll
        for (int j = 0; j < 4; j++) sc[j][0]=sc[j][1]=sc[j][2]=sc[j][3]=0.f;

        #pragma unroll
        for (int kk = 0; kk < 8; kk++){
            #pragma unroll
            for (int jp = 0; jp < 2; jp++){
                uint32_t r0,r1,r2,r3;
                ldsm_x4(r0,r1,r2,r3, kst + sc_off + (uint32_t)(jp*4352 + kk*32));
                mma16816(sc[2*jp  ], qf[kk], r0, r1);
                mma16816(sc[2*jp+1], qf[kk], r2, r3);
            }
        }

        // causal mask: only the globally-last tile (tile 127) is partial
        if (tile0 + t == 127){
            const int r0q = lane >> 2;
            #pragma unroll
            for (int j = 0; j < 4; j++){
                const int col = 8*j + (lane&3)*2;
                if (col     > 16 + r0q) sc[j][0] = -1e30f;
                if (col + 1 > 16 + r0q) sc[j][1] = -1e30f;
                if (col     > 24 + r0q) sc[j][2] = -1e30f;
                if (col + 1 > 24 + r0q) sc[j][3] = -1e30f;
            }
        }

        // ---- online softmax (base 2)
        float mx0 = fmaxf(fmaxf(sc[0][0],sc[0][1]), fmaxf(sc[1][0],sc[1][1]));
        mx0 = fmaxf(mx0, fmaxf(fmaxf(sc[2][0],sc[2][1]), fmaxf(sc[3][0],sc[3][1])));
        float mx1 = fmaxf(fmaxf(sc[0][2],sc[0][3]), fmaxf(sc[1][2],sc[1][3]));
        mx1 = fmaxf(mx1, fmaxf(fmaxf(sc[2][2],sc[2][3]), fmaxf(sc[3][2],sc[3][3])));
        mx0 = fmaxf(mx0, __shfl_xor_sync(0xffffffffu, mx0, 1));
        mx0 = fmaxf(mx0, __shfl_xor_sync(0xffffffffu, mx0, 2));
        mx1 = fmaxf(mx1, __shfl_xor_sync(0xffffffffu, mx1, 1));
        mx1 = fmaxf(mx1, __shfl_xor_sync(0xffffffffu, mx1, 2));
        const float nm0 = fmaxf(m0, mx0), nm1 = fmaxf(m1, mx1);
        const float a0 = ex2f(m0 - nm0), a1 = ex2f(m1 - nm1);
        m0 = nm0; m1 = nm1;
        l0 *= a0; l1 *= a1;
        #pragma unroll
        for (int j = 0; j < 4; j++){
            sc[j][0] = ex2f(sc[j][0] - m0);
            sc[j][1] = ex2f(sc[j][1] - m0);
            sc[j][2] = ex2f(sc[j][2] - m1);
            sc[j][3] = ex2f(sc[j][3] - m1);
            l0 += sc[j][0] + sc[j][1];
            l1 += sc[j][2] + sc[j][3];
        }
        if (__ballot_sync(0xffffffffu, (a0 != 1.f) || (a1 != 1.f))){
            #pragma unroll
            for (int j = 0; j < 16; j++){
                o[j][0]*=a0; o[j][1]*=a0; o[j][2]*=a1; o[j][3]*=a1;
            }
        }

        // ---- O += P @ Vtile  (P C-frags map exactly onto A-frags; V B-frags via ldmatrix.trans)
        #pragma unroll
        for (int k2 = 0; k2 < 2; k2++){
            uint32_t pa[4];
            pa[0] = packh2(sc[2*k2  ][0], sc[2*k2  ][1]);
            pa[1] = packh2(sc[2*k2  ][2], sc[2*k2  ][3]);
            pa[2] = packh2(sc[2*k2+1][0], sc[2*k2+1][1]);
            pa[3] = packh2(sc[2*k2+1][2], sc[2*k2+1][3]);
            #pragma unroll
            for (int jdp = 0; jdp < 8; jdp++){
                uint32_t r0,r1,r2,r3;
                ldsm_x4t(r0,r1,r2,r3, vst + pv_off + (uint32_t)(k2*4352 + jdp*32));
                mma16816(o[2*jdp  ], pa, r0, r1);
                mma16816(o[2*jdp+1], pa, r2, r3);
            }
        }
        bar_arrive(7 + st, 192);            // signal EMPTY
    }

    // ---- epilogue: quad-reduce l, store UNNORMALIZED partial O + (m,l)
    l0 += __shfl_xor_sync(0xffffffffu, l0, 1);
    l0 += __shfl_xor_sync(0xffffffffu, l0, 2);
    l1 += __shfl_xor_sync(0xffffffffu, l1, 1);
    l1 += __shfl_xor_sync(0xffffffffu, l1, 2);

    const int r0 = lane >> 2;
    const int hq = h*kG + w;
    float* o0 = g_opart + (((size_t)(s*512 + b*kQ + r0    ))*4096) + hq*kD + (lane&3)*2;
    float* o1 = g_opart + (((size_t)(s*512 + b*kQ + r0 + 8))*4096) + hq*kD + (lane&3)*2;
    #pragma unroll
    for (int jd = 0; jd < 16; jd++){
        *(float2*)(o0 + jd*8) = make_float2(o[jd][0], o[jd][1]);
        *(float2*)(o1 + jd*8) = make_float2(o[jd][2], o[jd][3]);
    }
    if ((lane & 3) == 0){
        const int i0 = ((((s*kBatch + b)*kHq + hq)*kQ) + r0)*2;
        g_ml[i0]      = m0; g_ml[i0 + 1]  = l0;
        g_ml[i0 + 16] = m1; g_ml[i0 + 17] = l1;   // rows r0+8
    }
}

// merge kSplit partial results: out = sum_s 2^(m_s-m*) O_s / sum_s 2^(m_s-m*) l_s
__global__ __launch_bounds__(256)
void paged_gqa_combine(float* __restrict__ out)
{
    const int idx = blockIdx.x * 256 + threadIdx.x;     // [0, 512*1024)
    const int row = idx >> 10;            // b*16 + q
    const int c4  = idx & 1023;           // float4 column
    const int b   = row >> 4;
    const int qi  = row & 15;
    const int hq  = c4 >> 5;              // (c4*4) / 128

    float m[kSplit], l[kSplit];
    float mstar = -1e30f;
    #pragma unroll
    for (int s = 0; s < kSplit; s++){
        const int i0 = ((((s*kBatch + b)*kHq + hq)*kQ) + qi)*2;
        m[s] = g_ml[i0]; l[s] = g_ml[i0 + 1];
        mstar = fmaxf(mstar, m[s]);
    }
    float denom = 0.f;
    float4 acc = make_float4(0.f, 0.f, 0.f, 0.f);
    #pragma unroll
    for (int s = 0; s < kSplit; s++){
        const float wgt = ex2f(m[s] - mstar);
        denom += wgt * l[s];
        const float4 v = *(const float4*)(g_opart + ((size_t)(s*512 + row))*4096 + c4*4);
        acc.x += wgt*v.x; acc.y += wgt*v.y; acc.z += wgt*v.z; acc.w += wgt*v.w;
    }
    const float inv = 1.0f / denom;
    acc.x *= inv; acc.y *= inv; acc.z *= inv; acc.w *= inv;
    ((float4*)out)[idx] = acc;
}

extern "C" void kernel_launch(void* const* d_in, const int* in_sizes, int n_in,
                              void* d_out, int out_size)
{
    const float* q  = (const float*)d_in[0];   // [32,16,32,128] f32
    const float* kc = (const float*)d_in[1];   // [8192,16,8,128] f32
    const float* vc = (const float*)d_in[2];   // [8192,16,8,128] f32
    const int*   pt = (const int*)  d_in[3];   // [32,256] i32
    float* out = (float*)d_out;                // [512,4096] f32

    cudaFuncSetAttribute(paged_gqa_part,
                         cudaFuncAttributeMaxDynamicSharedMemorySize, kSmemBytes);
    paged_gqa_part<<<kItems, 192, kSmemBytes>>>(q, kc, vc, pt);
    paged_gqa_combine<<<(512*1024)/256, 256>>>(out);
}

// round 8
// speedup vs baseline: 4.7130x; 1.1964x over previous
#include <cuda_runtime.h>
#include <cuda_fp16.h>
#include <stdint.h>

// Problem constants (fixed by the reference)
#define kBatch 32
#define kQ     16
#define kHq    32
#define kHkv   8
#define kG     4
#define kD     128
#define kPage  16
#define kPPS   256
#define kK     4096
#define kTile  32

// fp16 smem tiles: row = 128 halves + 8 pad = 136 halves (272B)
#define kRowH   136
#define kTileH  (kTile*kRowH)        // 4352 halves per K or V tile
#define kStageH (2*kTileH)           // 8704 halves (K+V) per stage
#define kNStg   2
#define kSmemBytes (kNStg*kStageH*2 + 64*4)   // 34816 + 256 = 35072

// Split-KV schedule: 5 chunks; chunk s covers tiles [26s, 26s+nt), nt=26 (s<4) / 24 (s=4)
#define kSplit   5
#define kItems   (kBatch*kHkv*kSplit)   // 1280 CTAs, one item each (HW load balance)

// Scratch: unnormalized partial O + per-row (m, l) in log2 domain
__device__ float g_opart[(size_t)kSplit * 512 * 4096];        // 40 MB
__device__ float g_ml[kSplit * kBatch * kHq * kQ * 2];        // 320 KB

__device__ __forceinline__ uint32_t packh2(float lo, float hi){
    __half2 h = __floats2half2_rn(lo, hi);
    return *reinterpret_cast<uint32_t*>(&h);
}
__device__ __forceinline__ float ex2f(float x){
    float y; asm("ex2.approx.ftz.f32 %0, %1;" : "=f"(y) : "f"(x)); return y;
}
__device__ __forceinline__ void mma16816(float* c, const uint32_t* a, uint32_t b0, uint32_t b1){
    asm volatile(
      "mma.sync.aligned.m16n8k16.row.col.f32.f16.f16.f32 "
      "{%0,%1,%2,%3}, {%4,%5,%6,%7}, {%8,%9}, {%0,%1,%2,%3};\n"
      : "+f"(c[0]), "+f"(c[1]), "+f"(c[2]), "+f"(c[3])
      : "r"(a[0]), "r"(a[1]), "r"(a[2]), "r"(a[3]), "r"(b0), "r"(b1));
}
__device__ __forceinline__ void ldsm_x4(uint32_t& r0, uint32_t& r1, uint32_t& r2, uint32_t& r3, uint32_t a){
    asm volatile("ldmatrix.sync.aligned.m8n8.x4.shared.b16 {%0,%1,%2,%3}, [%4];"
                 : "=r"(r0),"=r"(r1),"=r"(r2),"=r"(r3) : "r"(a));
}
__device__ __forceinline__ void ldsm_x4t(uint32_t& r0, uint32_t& r1, uint32_t& r2, uint32_t& r3, uint32_t a){
    asm volatile("ldmatrix.sync.aligned.m8n8.x4.trans.shared.b16 {%0,%1,%2,%3}, [%4];"
                 : "=r"(r0),"=r"(r1),"=r"(r2),"=r"(r3) : "r"(a));
}
__device__ __forceinline__ void sts64(uint32_t addr, uint32_t a, uint32_t b){
    asm volatile("st.shared.v2.b32 [%0], {%1,%2};" :: "r"(addr), "r"(a), "r"(b));
}

__global__ __launch_bounds__(128, 2)
void paged_gqa_part(const float* __restrict__ q,
                    const float* __restrict__ kc,
                    const float* __restrict__ vc,
                    const int*   __restrict__ pt)
{
    extern __shared__ __align__(16) char smem[];
    int* pts = (int*)(smem + kNStg*kStageH*2);
    const uint32_t smem_s = (uint32_t)__cvta_generic_to_shared(smem);

    const int tid = threadIdx.x;
    const int w = tid >> 5, lane = tid & 31;
    const int item = blockIdx.x;
    const int s   = item >> 8;
    const int rem = item & 255;
    const int b   = rem >> 3;
    const int h   = rem & 7;
    const int tile0 = 26 * s;
    const int nt    = (s == 4) ? 24 : 26;

    // page-table slice (2 pages per tile)
    if (tid < 2*nt) pts[tid] = pt[b*kPPS + 2*tile0 + tid];
    __syncthreads();

    // per-thread staging geometry: 8 rows (w, w+4, ..., w+28), 4-float column slice
    const int co = lane * 4;                 // float (=half) column offset

    #define LOAD_K(t_, dst_) { _Pragma("unroll") for (int i_ = 0; i_ < 8; i_++){ \
        const int r_ = w + 4*i_; const int p_ = (t_)*kTile + r_;                  \
        dst_[i_] = *(const float4*)(kc + ((size_t)(pts[p_>>4]*kPage + (p_&15))*kHkv + h)*kD + co); } }
    #define LOAD_V(t_, dst_) { _Pragma("unroll") for (int i_ = 0; i_ < 8; i_++){ \
        const int r_ = w + 4*i_; const int p_ = (t_)*kTile + r_;                  \
        dst_[i_] = *(const float4*)(vc + ((size_t)(pts[p_>>4]*kPage + (p_&15))*kHkv + h)*kD + co); } }
    #define STS_K(st_, src_) { const uint32_t d0_ = smem_s + (uint32_t)((st_)*kStageH + co)*2;           \
        _Pragma("unroll") for (int i_ = 0; i_ < 8; i_++){ const int r_ = w + 4*i_;                        \
        sts64(d0_ + (uint32_t)(r_*kRowH)*2, packh2(src_[i_].x, src_[i_].y), packh2(src_[i_].z, src_[i_].w)); } }
    #define STS_V(st_, src_) { const uint32_t d0_ = smem_s + (uint32_t)((st_)*kStageH + kTileH + co)*2;   \
        _Pragma("unroll") for (int i_ = 0; i_ < 8; i_++){ const int r_ = w + 4*i_;                        \
        sts64(d0_ + (uint32_t)(r_*kRowH)*2, packh2(src_[i_].x, src_[i_].y), packh2(src_[i_].z, src_[i_].w)); } }

    float4 kb[8], vb[8];

    // stage tile 0 (Q-frag prep overlaps the load latency)
    LOAD_K(0, kb);
    LOAD_V(0, vb);

    // Q fragments, pre-scaled by log2e/sqrt(D); warp = GQA lane g
    const float scale = 1.4426950408889634f * rsqrtf((float)kD);
    uint32_t qf[8][4];
    {
        const int r0 = lane >> 2;
        const int c0 = (lane & 3) * 2;
        const float* q0 = q + (((size_t)(b*kQ + r0    ))*kHq + h*kG + w)*kD;
        const float* q1 = q + (((size_t)(b*kQ + r0 + 8))*kHq + h*kG + w)*kD;
        #pragma unroll
        for (int kk = 0; kk < 8; kk++){
            const int c = c0 + kk*16;
            float2 x0 = *(const float2*)(q0 + c);
            float2 x1 = *(const float2*)(q1 + c);
            float2 x2 = *(const float2*)(q0 + c + 8);
            float2 x3 = *(const float2*)(q1 + c + 8);
            qf[kk][0] = packh2(x0.x*scale, x0.y*scale);
            qf[kk][1] = packh2(x1.x*scale, x1.y*scale);
            qf[kk][2] = packh2(x2.x*scale, x2.y*scale);
            qf[kk][3] = packh2(x3.x*scale, x3.y*scale);
        }
    }

    STS_K(0, kb);
    STS_V(0, vb);
    __syncthreads();

    // per-lane ldmatrix address bases (byte offsets within a tile)
    const int r8  = lane & 7;
    const int b8  = (lane >> 3) & 1;
    const int b16 = (lane >> 4) & 1;
    const uint32_t sc_off = (uint32_t)(((b16*8 + r8)*kRowH + b8*8)  * 2); // score: non-trans on K
    const uint32_t pv_off = (uint32_t)(((b8*8  + r8)*kRowH + b16*8) * 2); // PV: trans on V

    float o[16][4];
    #pragma unroll
    for (int j = 0; j < 16; j++){ o[j][0]=o[j][1]=o[j][2]=o[j][3]=0.f; }
    float m0 = -1e30f, m1 = -1e30f, l0 = 0.f, l1 = 0.f;

    #pragma unroll 1
    for (int t = 0; t < nt; t++){
        const int st = t & 1;
        const uint32_t kst = smem_s + (uint32_t)(st*kStageH)*2;
        const uint32_t vst = kst + (uint32_t)kTileH*2;
        const bool more = (t + 1 < nt);

        // stage t+1 K loads now; latency hides behind score compute
        if (more) LOAD_K(t+1, kb);

        // ---- scores S[16 x 32] = Qw @ Ktile^T  (log2-scaled)
        float sc[4][4];
        #pragma unroll
        for (int j = 0; j < 4; j++) sc[j][0]=sc[j][1]=sc[j][2]=sc[j][3]=0.f;

        #pragma unroll
        for (int kk = 0; kk < 8; kk++){
            #pragma unroll
            for (int jp = 0; jp < 2; jp++){
                uint32_t r0,r1,r2,r3;
                ldsm_x4(r0,r1,r2,r3, kst + sc_off + (uint32_t)(jp*4352 + kk*32));
                mma16816(sc[2*jp  ], qf[kk], r0, r1);
                mma16816(sc[2*jp+1], qf[kk], r2, r3);
            }
        }

        // drain K regs into the other stage; start V loads for t+1
        if (more){
            STS_K(st^1, kb);
            LOAD_V(t+1, vb);
        }

        // causal mask: only the globally-last tile (tile 127) is partial
        if (tile0 + t == 127){
            const int r0q = lane >> 2;
            #pragma unroll
            for (int j = 0; j < 4; j++){
                const int col = 8*j + (lane&3)*2;
                if (col     > 16 + r0q) sc[j][0] = -1e30f;
                if (col + 1 > 16 + r0q) sc[j][1] = -1e30f;
                if (col     > 24 + r0q) sc[j][2] = -1e30f;
                if (col + 1 > 24 + r0q) sc[j][3] = -1e30f;
            }
        }

        // ---- online softmax (base 2)
        float mx0 = fmaxf(fmaxf(sc[0][0],sc[0][1]), fmaxf(sc[1][0],sc[1][1]));
        mx0 = fmaxf(mx0, fmaxf(fmaxf(sc[2][0],sc[2][1]), fmaxf(sc[3][0],sc[3][1])));
        float mx1 = fmaxf(fmaxf(sc[0][2],sc[0][3]), fmaxf(sc[1][2],sc[1][3]));
        mx1 = fmaxf(mx1, fmaxf(fmaxf(sc[2][2],sc[2][3]), fmaxf(sc[3][2],sc[3][3])));
        mx0 = fmaxf(mx0, __shfl_xor_sync(0xffffffffu, mx0, 1));
        mx0 = fmaxf(mx0, __shfl_xor_sync(0xffffffffu, mx0, 2));
        mx1 = fmaxf(mx1, __shfl_xor_sync(0xffffffffu, mx1, 1));
        mx1 = fmaxf(mx1, __shfl_xor_sync(0xffffffffu, mx1, 2));
        const float nm0 = fmaxf(m0, mx0), nm1 = fmaxf(m1, mx1);
        const float a0 = ex2f(m0 - nm0), a1 = ex2f(m1 - nm1);
        m0 = nm0; m1 = nm1;
        l0 *= a0; l1 *= a1;
        #pragma unroll
        for (int j = 0; j < 4; j++){
            sc[j][0] = ex2f(sc[j][0] - m0);
            sc[j][1] = ex2f(sc[j][1] - m0);
            sc[j][2] = ex2f(sc[j][2] - m1);
            sc[j][3] = ex2f(sc[j][3] - m1);
            l0 += sc[j][0] + sc[j][1];
            l1 += sc[j][2] + sc[j][3];
        }
        if (__ballot_sync(0xffffffffu, (a0 != 1.f) || (a1 != 1.f))){
            #pragma unroll
            for (int j = 0; j < 16; j++){
                o[j][0]*=a0; o[j][1]*=a0; o[j][2]*=a1; o[j][3]*=a1;
            }
        }

        // ---- O += P @ Vtile  (P C-frags map exactly onto A-frags; V B-frags via ldmatrix.trans)
        #pragma unroll
        for (int k2 = 0; k2 < 2; k2++){
            uint32_t pa[4];
            pa[0] = packh2(sc[2*k2  ][0], sc[2*k2  ][1]);
            pa[1] = packh2(sc[2*k2  ][2], sc[2*k2  ][3]);
            pa[2] = packh2(sc[2*k2+1][0], sc[2*k2+1][1]);
            pa[3] = packh2(sc[2*k2+1][2], sc[2*k2+1][3]);
            #pragma unroll
            for (int jdp = 0; jdp < 8; jdp++){
                uint32_t r0,r1,r2,r3;
                ldsm_x4t(r0,r1,r2,r3, vst + pv_off + (uint32_t)(k2*4352 + jdp*32));
                mma16816(o[2*jdp  ], pa, r0, r1);
                mma16816(o[2*jdp+1], pa, r2, r3);
            }
        }

        // drain V regs; one barrier per tile covers both buffer hazards
        if (more) STS_V(st^1, vb);
        __syncthreads();
    }

    // ---- epilogue: quad-reduce l, store UNNORMALIZED partial O + (m,l)
    l0 += __shfl_xor_sync(0xffffffffu, l0, 1);
    l0 += __shfl_xor_sync(0xffffffffu, l0, 2);
    l1 += __shfl_xor_sync(0xffffffffu, l1, 1);
    l1 += __shfl_xor_sync(0xffffffffu, l1, 2);

    const int r0 = lane >> 2;
    const int hq = h*kG + w;
    float* o0 = g_opart + (((size_t)(s*512 + b*kQ + r0    ))*4096) + hq*kD + (lane&3)*2;
    float* o1 = g_opart + (((size_t)(s*512 + b*kQ + r0 + 8))*4096) + hq*kD + (lane&3)*2;
    #pragma unroll
    for (int jd = 0; jd < 16; jd++){
        *(float2*)(o0 + jd*8) = make_float2(o[jd][0], o[jd][1]);
        *(float2*)(o1 + jd*8) = make_float2(o[jd][2], o[jd][3]);
    }
    if ((lane & 3) == 0){
        const int i0 = ((((s*kBatch + b)*kHq + hq)*kQ) + r0)*2;
        g_ml[i0]      = m0; g_ml[i0 + 1]  = l0;
        g_ml[i0 + 16] = m1; g_ml[i0 + 17] = l1;   // rows r0+8
    }
}

// merge kSplit partial results: out = sum_s 2^(m_s-m*) O_s / sum_s 2^(m_s-m*) l_s
__global__ __launch_bounds__(256)
void paged_gqa_combine(float* __restrict__ out)
{
    const int idx = blockIdx.x * 256 + threadIdx.x;     // [0, 512*1024)
    const int row = idx >> 10;            // b*16 + q
    const int c4  = idx & 1023;           // float4 column
    const int b   = row >> 4;
    const int qi  = row & 15;
    const int hq  = c4 >> 5;              // (c4*4) / 128

    float m[kSplit], l[kSplit];
    float mstar = -1e30f;
    #pragma unroll
    for (int s = 0; s < kSplit; s++){
        const int i0 = ((((s*kBatch + b)*kHq + hq)*kQ) + qi)*2;
        m[s] = g_ml[i0]; l[s] = g_ml[i0 + 1];
        mstar = fmaxf(mstar, m[s]);
    }
    float denom = 0.f;
    float4 acc = make_float4(0.f, 0.f, 0.f, 0.f);
    #pragma unroll
    for (int s = 0; s < kSplit; s++){
        const float wgt = ex2f(m[s] - mstar);
        denom += wgt * l[s];
        const float4 v = *(const float4*)(g_opart + ((size_t)(s*512 + row))*4096 + c4*4);
        acc.x += wgt*v.x; acc.y += wgt*v.y; acc.z += wgt*v.z; acc.w += wgt*v.w;
    }
    const float inv = 1.0f / denom;
    acc.x *= inv; acc.y *= inv; acc.z *= inv; acc.w *= inv;
    ((float4*)out)[idx] = acc;
}

extern "C" void kernel_launch(void* const* d_in, const int* in_sizes, int n_in,
                              void* d_out, int out_size)
{
    const float* q  = (const float*)d_in[0];   // [32,16,32,128] f32
    const float* kc = (const float*)d_in[1];   // [8192,16,8,128] f32
    const float* vc = (const float*)d_in[2];   // [8192,16,8,128] f32
    const int*   pt = (const int*)  d_in[3];   // [32,256] i32
    float* out = (float*)d_out;                // [512,4096] f32

    cudaFuncSetAttribute(paged_gqa_part,
                         cudaFuncAttributeMaxDynamicSharedMemorySize, kSmemBytes);
    paged_gqa_part<<<kItems, 128, kSmemBytes>>>(q, kc, vc, pt);
    paged_gqa_combine<<<(512*1024)/256, 256>>>(out);
}

// round 9
// speedup vs baseline: 5.3440x; 1.1339x over previous
#include <cuda_runtime.h>
#include <cuda_fp16.h>
#include <stdint.h>

// Problem constants (fixed by the reference)
#define kBatch 32
#define kQ     16
#define kHq    32
#define kHkv   8
#define kG     4
#define kD     128
#define kPage  16
#define kPPS   256
#define kK     4096
#define kTile  32

// K: fp32 smem ring via cp.async. row = 128 + 8 pad = 136 floats (544B)
#define kKStrF   136
#define kKStageF (kTile*kKStrF)       // 4352 floats per K stage
#define kNStgK   3
// V: fp16 smem double-buffer via register staging. row = 136 halves (272B)
#define kRowH    136
#define kVTileH  (kTile*kRowH)        // 4352 halves per V stage (8704 B)
#define kNStgV   2

#define kVBase   (kNStgK*kKStageF*4)            // 52224 B
#define kPtsBase (kVBase + kNStgV*kVTileH*2)    // 69632 B
#define kSmemBytes (kPtsBase + 64*4)            // 69888 B -> 3 CTAs/SM

// Split-KV schedule: 5 chunks; chunk s covers tiles [26s, 26s+nt), nt=26 (s<4) / 24 (s=4)
#define kSplit   5
#define kItems   (kBatch*kHkv*kSplit)   // 1280 CTAs, one item each

// Scratch: unnormalized partial O + per-row (m, l) in log2 domain
__device__ float g_opart[(size_t)kSplit * 512 * 4096];        // 40 MB
__device__ float g_ml[kSplit * kBatch * kHq * kQ * 2];        // 320 KB

__device__ __forceinline__ uint32_t packh2(float lo, float hi){
    __half2 h = __floats2half2_rn(lo, hi);
    return *reinterpret_cast<uint32_t*>(&h);
}
__device__ __forceinline__ float ex2f(float x){
    float y; asm("ex2.approx.ftz.f32 %0, %1;" : "=f"(y) : "f"(x)); return y;
}
__device__ __forceinline__ void mma16816(float* c, const uint32_t* a, uint32_t b0, uint32_t b1){
    asm volatile(
      "mma.sync.aligned.m16n8k16.row.col.f32.f16.f16.f32 "
      "{%0,%1,%2,%3}, {%4,%5,%6,%7}, {%8,%9}, {%0,%1,%2,%3};\n"
      : "+f"(c[0]), "+f"(c[1]), "+f"(c[2]), "+f"(c[3])
      : "r"(a[0]), "r"(a[1]), "r"(a[2]), "r"(a[3]), "r"(b0), "r"(b1));
}
__device__ __forceinline__ void ldsm_x4t(uint32_t& r0, uint32_t& r1, uint32_t& r2, uint32_t& r3, uint32_t a){
    asm volatile("ldmatrix.sync.aligned.m8n8.x4.trans.shared.b16 {%0,%1,%2,%3}, [%4];"
                 : "=r"(r0),"=r"(r1),"=r"(r2),"=r"(r3) : "r"(a));
}
__device__ __forceinline__ void sts64(uint32_t addr, uint32_t a, uint32_t b){
    asm volatile("st.shared.v2.b32 [%0], {%1,%2};" :: "r"(addr), "r"(a), "r"(b));
}
__device__ __forceinline__ void cp16(uint32_t dst, const float* src){
    asm volatile("cp.async.cg.shared.global [%0], [%1], 16;\n" :: "r"(dst), "l"(src));
}

__global__ __launch_bounds__(128, 3)
void paged_gqa_part(const float* __restrict__ q,
                    const float* __restrict__ kc,
                    const float* __restrict__ vc,
                    const int*   __restrict__ pt)
{
    extern __shared__ __align__(16) char smem[];
    float* ksm = (float*)smem;
    int*   pts = (int*)(smem + kPtsBase);
    const uint32_t smem_s  = (uint32_t)__cvta_generic_to_shared(smem);
    const uint32_t vbase_s = smem_s + kVBase;

    const int tid = threadIdx.x;
    const int w = tid >> 5, lane = tid & 31;
    const int item = blockIdx.x;
    const int s   = item >> 8;
    const int rem = item & 255;
    const int b   = rem >> 3;
    const int h   = rem & 7;
    const int tile0 = 26 * s;
    const int nt    = (s == 4) ? 24 : 26;

    // page-table slice (2 pages per tile)
    if (tid < 2*nt) pts[tid] = pt[b*kPPS + 2*tile0 + tid];
    __syncthreads();

    const int co = lane * 4;                 // float/half column offset (16B per lane)

    // K: cp.async fp32, one commit group per tile, 3-stage ring
    #define LOAD_K_ASYNC(t_) do{ const int st_=(t_)%kNStgK;                                   \
        _Pragma("unroll") for(int i_=0;i_<8;i_++){ const int r_=w+4*i_; const int p_=(t_)*kTile+r_; \
            const float* src_ = kc + ((size_t)(pts[p_>>4]*kPage+(p_&15))*kHkv+h)*kD + co;     \
            cp16(smem_s + (uint32_t)(st_*kKStageF + r_*kKStrF + co)*4, src_); }               \
        asm volatile("cp.async.commit_group;\n"); }while(0)

    // V: register batch-load (8 independent LDG.128), then convert+STS fp16
    #define LOAD_V_REG(t_) { _Pragma("unroll") for(int i_=0;i_<8;i_++){                        \
        const int r_=w+4*i_; const int p_=(t_)*kTile+r_;                                       \
        vb[i_] = *(const float4*)(vc + ((size_t)(pts[p_>>4]*kPage+(p_&15))*kHkv+h)*kD + co); } }
    #define STS_V_F16(t_) { const uint32_t d0_ = vbase_s + (uint32_t)((((t_)&1)*kVTileH) + co)*2; \
        _Pragma("unroll") for(int i_=0;i_<8;i_++){ const int r_=w+4*i_;                        \
        sts64(d0_ + (uint32_t)(r_*kRowH)*2, packh2(vb[i_].x,vb[i_].y), packh2(vb[i_].z,vb[i_].w)); } }

    float4 vb[8];

    // prologue: 2 K tiles in flight; V tile 0 loads overlap Q-frag prep
    LOAD_K_ASYNC(0);
    LOAD_K_ASYNC(1);
    LOAD_V_REG(0);

    // Q fragments, pre-scaled by log2e/sqrt(D); warp = GQA lane g
    const float scale = 1.4426950408889634f * rsqrtf((float)kD);
    uint32_t qf[8][4];
    {
        const int r0 = lane >> 2;
        const int c0 = (lane & 3) * 2;
        const float* q0 = q + (((size_t)(b*kQ + r0    ))*kHq + h*kG + w)*kD;
        const float* q1 = q + (((size_t)(b*kQ + r0 + 8))*kHq + h*kG + w)*kD;
        #pragma unroll
        for (int kk = 0; kk < 8; kk++){
            const int c = c0 + kk*16;
            float2 x0 = *(const float2*)(q0 + c);
            float2 x1 = *(const float2*)(q1 + c);
            float2 x2 = *(const float2*)(q0 + c + 8);
            float2 x3 = *(const float2*)(q1 + c + 8);
            qf[kk][0] = packh2(x0.x*scale, x0.y*scale);
            qf[kk][1] = packh2(x1.x*scale, x1.y*scale);
            qf[kk][2] = packh2(x2.x*scale, x2.y*scale);
            qf[kk][3] = packh2(x3.x*scale, x3.y*scale);
        }
    }
    STS_V_F16(0);

    // per-lane ldmatrix.trans address base for PV (byte offset within a V stage)
    const int r8  = lane & 7;
    const int b8  = (lane >> 3) & 1;
    const int b16 = (lane >> 4) & 1;
    const uint32_t pv_off = (uint32_t)(((b8*8 + r8)*kRowH + b16*8) * 2);

    float o[16][4];
    #pragma unroll
    for (int j = 0; j < 16; j++){ o[j][0]=o[j][1]=o[j][2]=o[j][3]=0.f; }
    float m0 = -1e30f, m1 = -1e30f, l0 = 0.f, l1 = 0.f;

    #pragma unroll 1
    for (int t = 0; t < nt; t++){
        if (t + 2 < nt){
            LOAD_K_ASYNC(t + 2);
            asm volatile("cp.async.wait_group 2;\n");
        } else if (t + 1 < nt){
            asm volatile("cp.async.wait_group 1;\n");
        } else {
            asm volatile("cp.async.wait_group 0;\n");
        }
        __syncthreads();     // K(t) + V(t) (STS'd last iter / prologue) visible

        // V loads for t+1 issued NOW: ~score+softmax (>600cyc) of latency cover
        const bool more = (t + 1 < nt);
        if (more) LOAD_V_REG(t+1);

        const float* ks = ksm + (t % kNStgK)*kKStageF;

        // ---- scores S[16 x 32] = Qw @ Ktile^T  (log2-scaled; fp32 smem B-frags)
        float sc[4][4];
        #pragma unroll
        for (int j = 0; j < 4; j++) sc[j][0]=sc[j][1]=sc[j][2]=sc[j][3]=0.f;

        #pragma unroll
        for (int kk = 0; kk < 8; kk++){
            #pragma unroll
            for (int j = 0; j < 4; j++){
                const float* bp = ks + (8*j + (lane>>2))*kKStrF + kk*16 + (lane&3)*2;
                float2 x = *(const float2*)bp;
                float2 y = *(const float2*)(bp + 8);
                mma16816(sc[j], qf[kk], packh2(x.x, x.y), packh2(y.x, y.y));
            }
        }

        // causal mask: only the globally-last tile (tile 127) is partial
        if (tile0 + t == 127){
            const int r0q = lane >> 2;
            #pragma unroll
            for (int j = 0; j < 4; j++){
                const int col = 8*j + (lane&3)*2;
                if (col     > 16 + r0q) sc[j][0] = -1e30f;
                if (col + 1 > 16 + r0q) sc[j][1] = -1e30f;
                if (col     > 24 + r0q) sc[j][2] = -1e30f;
                if (col + 1 > 24 + r0q) sc[j][3] = -1e30f;
            }
        }

        // ---- online softmax (base 2)
        float mx0 = fmaxf(fmaxf(sc[0][0],sc[0][1]), fmaxf(sc[1][0],sc[1][1]));
        mx0 = fmaxf(mx0, fmaxf(fmaxf(sc[2][0],sc[2][1]), fmaxf(sc[3][0],sc[3][1])));
        float mx1 = fmaxf(fmaxf(sc[0][2],sc[0][3]), fmaxf(sc[1][2],sc[1][3]));
        mx1 = fmaxf(mx1, fmaxf(fmaxf(sc[2][2],sc[2][3]), fmaxf(sc[3][2],sc[3][3])));
        mx0 = fmaxf(mx0, __shfl_xor_sync(0xffffffffu, mx0, 1));
        mx0 = fmaxf(mx0, __shfl_xor_sync(0xffffffffu, mx0, 2));
        mx1 = fmaxf(mx1, __shfl_xor_sync(0xffffffffu, mx1, 1));
        mx1 = fmaxf(mx1, __shfl_xor_sync(0xffffffffu, mx1, 2));
        const float nm0 = fmaxf(m0, mx0), nm1 = fmaxf(m1, mx1);
        const float a0 = ex2f(m0 - nm0), a1 = ex2f(m1 - nm1);
        m0 = nm0; m1 = nm1;
        l0 *= a0; l1 *= a1;
        #pragma unroll
        for (int j = 0; j < 4; j++){
            sc[j][0] = ex2f(sc[j][0] - m0);
            sc[j][1] = ex2f(sc[j][1] - m0);
            sc[j][2] = ex2f(sc[j][2] - m1);
            sc[j][3] = ex2f(sc[j][3] - m1);
            l0 += sc[j][0] + sc[j][1];
            l1 += sc[j][2] + sc[j][3];
        }
        if (__ballot_sync(0xffffffffu, (a0 != 1.f) || (a1 != 1.f))){
            #pragma unroll
            for (int j = 0; j < 16; j++){
                o[j][0]*=a0; o[j][1]*=a0; o[j][2]*=a1; o[j][3]*=a1;
            }
        }

        // drain V(t+1) regs into the other fp16 stage (scoreboard: loads now ~landed)
        if (more) STS_V_F16(t+1);

        // ---- O += P @ Vtile  (P C-frags map onto A-frags; V B-frags via ldmatrix.trans fp16)
        const uint32_t vst = vbase_s + (uint32_t)((t & 1)*kVTileH)*2;
        #pragma unroll
        for (int k2 = 0; k2 < 2; k2++){
            uint32_t pa[4];
            pa[0] = packh2(sc[2*k2  ][0], sc[2*k2  ][1]);
            pa[1] = packh2(sc[2*k2  ][2], sc[2*k2  ][3]);
            pa[2] = packh2(sc[2*k2+1][0], sc[2*k2+1][1]);
            pa[3] = packh2(sc[2*k2+1][2], sc[2*k2+1][3]);
            #pragma unroll
            for (int jdp = 0; jdp < 8; jdp++){
                uint32_t r0,r1,r2,r3;
                ldsm_x4t(r0,r1,r2,r3, vst + pv_off + (uint32_t)(k2*4352 + jdp*32));
                mma16816(o[2*jdp  ], pa, r0, r1);
                mma16816(o[2*jdp+1], pa, r2, r3);
            }
        }
        __syncthreads();     // stage-reuse fence (K stage (t+2)%3 issue next iter; V stage writes)
    }

    // ---- epilogue: quad-reduce l, store UNNORMALIZED partial O + (m,l)
    l0 += __shfl_xor_sync(0xffffffffu, l0, 1);
    l0 += __shfl_xor_sync(0xffffffffu, l0, 2);
    l1 += __shfl_xor_sync(0xffffffffu, l1, 1);
    l1 += __shfl_xor_sync(0xffffffffu, l1, 2);

    const int r0 = lane >> 2;
    const int hq = h*kG + w;
    float* o0 = g_opart + (((size_t)(s*512 + b*kQ + r0    ))*4096) + hq*kD + (lane&3)*2;
    float* o1 = g_opart + (((size_t)(s*512 + b*kQ + r0 + 8))*4096) + hq*kD + (lane&3)*2;
    #pragma unroll
    for (int jd = 0; jd < 16; jd++){
        *(float2*)(o0 + jd*8) = make_float2(o[jd][0], o[jd][1]);
        *(float2*)(o1 + jd*8) = make_float2(o[jd][2], o[jd][3]);
    }
    if ((lane & 3) == 0){
        const int i0 = ((((s*kBatch + b)*kHq + hq)*kQ) + r0)*2;
        g_ml[i0]      = m0; g_ml[i0 + 1]  = l0;
        g_ml[i0 + 16] = m1; g_ml[i0 + 17] = l1;   // rows r0+8
    }
}

// merge kSplit partial results: out = sum_s 2^(m_s-m*) O_s / sum_s 2^(m_s-m*) l_s
__global__ __launch_bounds__(256)
void paged_gqa_combine(float* __restrict__ out)
{
    const int idx = blockIdx.x * 256 + threadIdx.x;     // [0, 512*1024)
    const int row = idx >> 10;            // b*16 + q
    const int c4  = idx & 1023;           // float4 column
    const int b   = row >> 4;
    const int qi  = row & 15;
    const int hq  = c4 >> 5;              // (c4*4) / 128

    float m[kSplit], l[kSplit];
    float mstar = -1e30f;
    #pragma unroll
    for (int s = 0; s < kSplit; s++){
        const int i0 = ((((s*kBatch + b)*kHq + hq)*kQ) + qi)*2;
        m[s] = g_ml[i0]; l[s] = g_ml[i0 + 1];
        mstar = fmaxf(mstar, m[s]);
    }
    float denom = 0.f;
    float4 acc = make_float4(0.f, 0.f, 0.f, 0.f);
    #pragma unroll
    for (int s = 0; s < kSplit; s++){
        const float wgt = ex2f(m[s] - mstar);
        denom += wgt * l[s];
        const float4 v = *(const float4*)(g_opart + ((size_t)(s*512 + row))*4096 + c4*4);
        acc.x += wgt*v.x; acc.y += wgt*v.y; acc.z += wgt*v.z; acc.w += wgt*v.w;
    }
    const float inv = 1.0f / denom;
    acc.x *= inv; acc.y *= inv; acc.z *= inv; acc.w *= inv;
    ((float4*)out)[idx] = acc;
}

extern "C" void kernel_launch(void* const* d_in, const int* in_sizes, int n_in,
                              void* d_out, int out_size)
{
    const float* q  = (const float*)d_in[0];   // [32,16,32,128] f32
    const float* kc = (const float*)d_in[1];   // [8192,16,8,128] f32
    const float* vc = (const float*)d_in[2];   // [8192,16,8,128] f32
    const int*   pt = (const int*)  d_in[3];   // [32,256] i32
    float* out = (float*)d_out;                // [512,4096] f32

    cudaFuncSetAttribute(paged_gqa_part,
                         cudaFuncAttributeMaxDynamicSharedMemorySize, kSmemBytes);
    paged_gqa_part<<<kItems, 128, kSmemBytes>>>(q, kc, vc, pt);
    paged_gqa_combine<<<(512*1024)/256, 256>>>(out);
}

// round 10
// speedup vs baseline: 6.1810x; 1.1566x over previous
#include <cuda_runtime.h>
#include <cuda_fp16.h>
#include <stdint.h>

// Problem constants (fixed by the reference)
#define kBatch 32
#define kQ     16
#define kHq    32
#define kHkv   8
#define kG     4
#define kD     128
#define kPage  16
#define kPPS   256
#define kK     4096
#define kTile  32
#define kKStr  136            // K smem row stride (floats) — conflict-free score B-frag LDS.64
#define kVStr  132            // V smem row stride (floats) — conflict-free PV B-frag LDS.32
#define kStages 2
#define kSmemBytes (4*(kStages*kTile*(kKStr+kVStr)) + 4*64)  // 68864 B -> 3 CTAs/SM

// Split-KV: 4 chunks x 32 tiles; 1024 equal CTAs, HW-scheduled (non-persistent)
#define kSplit   4
#define kNTc     32                      // tiles per chunk
#define kItems   (kBatch*kHkv*kSplit)    // 1024

// Scratch: UNNORMALIZED partial O in fp16 + per-row (m, l) fp32 (log2 domain)
__device__ __half g_opart[(size_t)kSplit * 512 * 4096];       // 16 MB
__device__ float  g_ml[kSplit * kBatch * kHq * kQ * 2];       // 256 KB

__device__ __forceinline__ uint32_t packh2(float lo, float hi){
    __half2 h = __floats2half2_rn(lo, hi);
    return *reinterpret_cast<uint32_t*>(&h);
}
__device__ __forceinline__ float ex2f(float x){
    float y; asm("ex2.approx.ftz.f32 %0, %1;" : "=f"(y) : "f"(x)); return y;
}
__device__ __forceinline__ void mma16816(float* c, const uint32_t* a, uint32_t b0, uint32_t b1){
    asm volatile(
      "mma.sync.aligned.m16n8k16.row.col.f32.f16.f16.f32 "
      "{%0,%1,%2,%3}, {%4,%5,%6,%7}, {%8,%9}, {%0,%1,%2,%3};\n"
      : "+f"(c[0]), "+f"(c[1]), "+f"(c[2]), "+f"(c[3])
      : "r"(a[0]), "r"(a[1]), "r"(a[2]), "r"(a[3]), "r"(b0), "r"(b1));
}
__device__ __forceinline__ void cp16(uint32_t dst, const float* src){
    asm volatile("cp.async.cg.shared.global [%0], [%1], 16;\n" :: "r"(dst), "l"(src));
}

__global__ __launch_bounds__(128, 3)
void paged_gqa_part(const float* __restrict__ q,
                    const float* __restrict__ kc,
                    const float* __restrict__ vc,
                    const int*   __restrict__ pt)
{
    extern __shared__ float smem[];
    float* ksm = smem;
    float* vsm = smem + kStages*kTile*kKStr;
    int*   pts = (int*)(smem + kStages*kTile*(kKStr+kVStr));   // 64 page slots

    const int tid = threadIdx.x;
    const int w = tid >> 5, lane = tid & 31;
    const uint32_t ksm_s = (uint32_t)__cvta_generic_to_shared(ksm);
    const uint32_t vsm_s = (uint32_t)__cvta_generic_to_shared(vsm);
    const int ld_row0  = tid >> 5;        // 0..3
    const int ld_chunk = (tid & 31) * 4;  // float offset (16B per lane)
    const float scale = 1.4426950408889634f * rsqrtf((float)kD);

    const int item = blockIdx.x;
    const int s   = item >> 8;            // chunk 0..3
    const int rem = item & 255;
    const int b   = rem >> 3;
    const int h   = rem & 7;
    const int tile0 = kNTc * s;

    // ---- per-item page-table slice (2 pages per tile, 64 pages per chunk)
    if (tid < 64) pts[tid] = pt[b*kPPS + 64*s + tid];
    __syncthreads();

    // ---- Q fragments for this (b,h), warp = GQA lane g, pre-scaled
    uint32_t qf[8][4];
    {
        const int r0 = lane >> 2;
        const int c0 = (lane & 3) * 2;
        const float* q0 = q + (((size_t)(b*kQ + r0    ))*kHq + h*kG + w)*kD;
        const float* q1 = q + (((size_t)(b*kQ + r0 + 8))*kHq + h*kG + w)*kD;
        #pragma unroll
        for (int kk = 0; kk < 8; kk++){
            const int c = c0 + kk*16;
            float2 x0 = *(const float2*)(q0 + c);
            float2 x1 = *(const float2*)(q1 + c);
            float2 x2 = *(const float2*)(q0 + c + 8);
            float2 x3 = *(const float2*)(q1 + c + 8);
            qf[kk][0] = packh2(x0.x*scale, x0.y*scale);
            qf[kk][1] = packh2(x1.x*scale, x1.y*scale);
            qf[kk][2] = packh2(x2.x*scale, x2.y*scale);
            qf[kk][3] = packh2(x3.x*scale, x3.y*scale);
        }
    }

    float o[16][4];
    #pragma unroll
    for (int j = 0; j < 16; j++){ o[j][0]=o[j][1]=o[j][2]=o[j][3]=0.f; }
    float m0 = -1e30f, m1 = -1e30f, l0 = 0.f, l1 = 0.f;

    #define LOAD_TILE(t_) do {                                                        \
        const int st_ = (t_) & 1;                                                     \
        _Pragma("unroll")                                                             \
        for (int i_ = 0; i_ < 8; i_++){                                               \
            const int r_ = ld_row0 + i_*4;                                            \
            const int p_ = (t_)*kTile + r_;                                           \
            const int base_ = ((pts[p_ >> 4]*kPage + (p_ & 15))*kHkv + h)*kD + ld_chunk; \
            cp16(ksm_s + (uint32_t)(st_*kTile*kKStr + r_*kKStr + ld_chunk)*4, kc + base_); \
            cp16(vsm_s + (uint32_t)(st_*kTile*kVStr + r_*kVStr + ld_chunk)*4, vc + base_); \
        }                                                                             \
        asm volatile("cp.async.commit_group;\n");                                     \
    } while(0)

    LOAD_TILE(0);

    #pragma unroll 1
    for (int t = 0; t < kNTc; t++){
        if (t + 1 < kNTc){
            LOAD_TILE(t + 1);
            asm volatile("cp.async.wait_group 1;\n");
        } else {
            asm volatile("cp.async.wait_group 0;\n");
        }
        __syncthreads();

        const float* ks = ksm + (t & 1)*kTile*kKStr;
        const float* vs = vsm + (t & 1)*kTile*kVStr;

        // ---- scores S[16 x 32] = Qw @ Ktile^T  (log2-scaled)
        float sc[4][4];
        #pragma unroll
        for (int j = 0; j < 4; j++) sc[j][0]=sc[j][1]=sc[j][2]=sc[j][3]=0.f;

        #pragma unroll
        for (int kk = 0; kk < 8; kk++){
            #pragma unroll
            for (int j = 0; j < 4; j++){
                const float* bp = ks + (8*j + (lane>>2))*kKStr + kk*16 + (lane&3)*2;
                float2 x = *(const float2*)bp;
                float2 y = *(const float2*)(bp + 8);
                mma16816(sc[j], qf[kk], packh2(x.x, x.y), packh2(y.x, y.y));
            }
        }

        // causal mask: only the globally-last tile (tile 127) is partial
        if (tile0 + t == 127){
            const int r0 = lane >> 2;
            #pragma unroll
            for (int j = 0; j < 4; j++){
                const int col = 8*j + (lane&3)*2;
                if (col     > 16 + r0) sc[j][0] = -1e30f;
                if (col + 1 > 16 + r0) sc[j][1] = -1e30f;
                if (col     > 24 + r0) sc[j][2] = -1e30f;
                if (col + 1 > 24 + r0) sc[j][3] = -1e30f;
            }
        }

        // ---- online softmax (base 2)
        float mx0 = fmaxf(fmaxf(sc[0][0],sc[0][1]), fmaxf(sc[1][0],sc[1][1]));
        mx0 = fmaxf(mx0, fmaxf(fmaxf(sc[2][0],sc[2][1]), fmaxf(sc[3][0],sc[3][1])));
        float mx1 = fmaxf(fmaxf(sc[0][2],sc[0][3]), fmaxf(sc[1][2],sc[1][3]));
        mx1 = fmaxf(mx1, fmaxf(fmaxf(sc[2][2],sc[2][3]), fmaxf(sc[3][2],sc[3][3])));
        mx0 = fmaxf(mx0, __shfl_xor_sync(0xffffffffu, mx0, 1));
        mx0 = fmaxf(mx0, __shfl_xor_sync(0xffffffffu, mx0, 2));
        mx1 = fmaxf(mx1, __shfl_xor_sync(0xffffffffu, mx1, 1));
        mx1 = fmaxf(mx1, __shfl_xor_sync(0xffffffffu, mx1, 2));
        const float nm0 = fmaxf(m0, mx0), nm1 = fmaxf(m1, mx1);
        const float a0 = ex2f(m0 - nm0), a1 = ex2f(m1 - nm1);
        m0 = nm0; m1 = nm1;
        l0 *= a0; l1 *= a1;
        #pragma unroll
        for (int j = 0; j < 4; j++){
            sc[j][0] = ex2f(sc[j][0] - m0);
            sc[j][1] = ex2f(sc[j][1] - m0);
            sc[j][2] = ex2f(sc[j][2] - m1);
            sc[j][3] = ex2f(sc[j][3] - m1);
            l0 += sc[j][0] + sc[j][1];
            l1 += sc[j][2] + sc[j][3];
        }
        if (__ballot_sync(0xffffffffu, (a0 != 1.f) || (a1 != 1.f))){
            #pragma unroll
            for (int j = 0; j < 16; j++){
                o[j][0]*=a0; o[j][1]*=a0; o[j][2]*=a1; o[j][3]*=a1;
            }
        }

        // ---- O += P @ Vtile  (P C-frags map exactly onto A-frags)
        #pragma unroll
        for (int k2 = 0; k2 < 2; k2++){
            uint32_t pa[4];
            pa[0] = packh2(sc[2*k2  ][0], sc[2*k2  ][1]);
            pa[1] = packh2(sc[2*k2  ][2], sc[2*k2  ][3]);
            pa[2] = packh2(sc[2*k2+1][0], sc[2*k2+1][1]);
            pa[3] = packh2(sc[2*k2+1][2], sc[2*k2+1][3]);
            const float* vb = vs + (k2*16 + (lane&3)*2)*kVStr + (lane>>2);
            #pragma unroll
            for (int jd = 0; jd < 16; jd++){
                const float* p0 = vb + jd*8;
                uint32_t b0 = packh2(p0[0],        p0[kVStr]);
                uint32_t b1 = packh2(p0[8*kVStr],  p0[9*kVStr]);
                mma16816(o[jd], pa, b0, b1);
            }
        }
        __syncthreads();
    }
    #undef LOAD_TILE

    // ---- epilogue: quad-reduce l, store UNNORMALIZED partial O (fp16) + (m,l)
    l0 += __shfl_xor_sync(0xffffffffu, l0, 1);
    l0 += __shfl_xor_sync(0xffffffffu, l0, 2);
    l1 += __shfl_xor_sync(0xffffffffu, l1, 1);
    l1 += __shfl_xor_sync(0xffffffffu, l1, 2);

    const int r0 = lane >> 2;
    const int hq = h*kG + w;
    __half* o0 = g_opart + (((size_t)(s*512 + b*kQ + r0    ))*4096) + hq*kD + (lane&3)*2;
    __half* o1 = g_opart + (((size_t)(s*512 + b*kQ + r0 + 8))*4096) + hq*kD + (lane&3)*2;
    #pragma unroll
    for (int jd = 0; jd < 16; jd++){
        *(uint32_t*)(o0 + jd*8) = packh2(o[jd][0], o[jd][1]);
        *(uint32_t*)(o1 + jd*8) = packh2(o[jd][2], o[jd][3]);
    }
    if ((lane & 3) == 0){
        const int i0 = ((((s*kBatch + b)*kHq + hq)*kQ) + r0)*2;
        g_ml[i0]      = m0; g_ml[i0 + 1]  = l0;
        g_ml[i0 + 16] = m1; g_ml[i0 + 17] = l1;   // rows r0+8
    }
}

// merge kSplit partial results: out = sum_s 2^(m_s-m*) O_s / sum_s 2^(m_s-m*) l_s
__global__ __launch_bounds__(256)
void paged_gqa_combine(float* __restrict__ out)
{
    const int idx = blockIdx.x * 256 + threadIdx.x;     // [0, 512*1024)
    const int row = idx >> 10;            // b*16 + q
    const int c4  = idx & 1023;           // 4-element column group
    const int b   = row >> 4;
    const int qi  = row & 15;
    const int hq  = c4 >> 5;              // (c4*4) / 128

    float m[kSplit], l[kSplit];
    float mstar = -1e30f;
    #pragma unroll
    for (int s = 0; s < kSplit; s++){
        const int i0 = ((((s*kBatch + b)*kHq + hq)*kQ) + qi)*2;
        m[s] = g_ml[i0]; l[s] = g_ml[i0 + 1];
        mstar = fmaxf(mstar, m[s]);
    }
    float denom = 0.f;
    float4 acc = make_float4(0.f, 0.f, 0.f, 0.f);
    #pragma unroll
    for (int s = 0; s < kSplit; s++){
        const float wgt = ex2f(m[s] - mstar);
        denom += wgt * l[s];
        const __half2* vp = (const __half2*)(g_opart + ((size_t)(s*512 + row))*4096 + c4*4);
        float2 v01 = __half22float2(vp[0]);
        float2 v23 = __half22float2(vp[1]);
        acc.x += wgt*v01.x; acc.y += wgt*v01.y; acc.z += wgt*v23.x; acc.w += wgt*v23.y;
    }
    const float inv = 1.0f / denom;
    acc.x *= inv; acc.y *= inv; acc.z *= inv; acc.w *= inv;
    ((float4*)out)[idx] = acc;
}

extern "C" void kernel_launch(void* const* d_in, const int* in_sizes, int n_in,
                              void* d_out, int out_size)
{
    const float* q  = (const float*)d_in[0];   // [32,16,32,128] f32
    const float* kc = (const float*)d_in[1];   // [8192,16,8,128] f32
    const float* vc = (const float*)d_in[2];   // [8192,16,8,128] f32
    const int*   pt = (const int*)  d_in[3];   // [32,256] i32
    float* out = (float*)d_out;                // [512,4096] f32

    cudaFuncSetAttribute(paged_gqa_part,
                         cudaFuncAttributeMaxDynamicSharedMemorySize, kSmemBytes);
    paged_gqa_part<<<kItems, 128, kSmemBytes>>>(q, kc, vc, pt);
    paged_gqa_combine<<<(512*1024)/256, 256>>>(out);
}